// round 1
// baseline (speedup 1.0000x reference)
#include <cuda_runtime.h>
#include <cuda_bf16.h>
#include <math.h>

// ---------------------------------------------------------------------------
// Problem constants (fixed by setup_inputs)
// ---------------------------------------------------------------------------
#define BATCH 1024
#define NSUP 16
#define TSTEPS 3
#define NLAT 6

// ---------------------------------------------------------------------------
// Scratch buffers (__device__ globals; no allocation allowed)
// ---------------------------------------------------------------------------
__device__ __align__(256) float g_pool1[BATCH * 16 * 14 * 14];   // 12.8 MB
__device__ __align__(256) float g_pool2[BATCH * 32 * 7 * 7];     // 6.4 MB (== flattened h)
__device__ __align__(256) float g_t1[BATCH * 1024];              // mid activations
__device__ __align__(256) float g_inp[BATCH * 512];
__device__ __align__(256) float g_out[BATCH * 512];
__device__ __align__(256) float g_lat[BATCH * 512];

// ---------------------------------------------------------------------------
// conv1 (1->16, 3x3 SAME) + ReLU + 2x2 maxpool fused.  out: (B,16,14,14)
// ---------------------------------------------------------------------------
__global__ void conv1_pool_kernel(const float* __restrict__ in,
                                  const float* __restrict__ w,
                                  const float* __restrict__ bias,
                                  float* __restrict__ out)
{
    int i = blockIdx.x * blockDim.x + threadIdx.x;
    const int total = BATCH * 16 * 14 * 14;
    if (i >= total) return;
    int x = i % 14;
    int y = (i / 14) % 14;
    int c = (i / 196) % 16;
    int b = i / (196 * 16);

    float wv[9];
#pragma unroll
    for (int j = 0; j < 9; j++) wv[j] = w[c * 9 + j];
    float bz = bias[c];
    const float* ip = in + (size_t)b * 784;

    float m = 0.0f;  // relu clamps each candidate to >= 0
#pragma unroll
    for (int dy = 0; dy < 2; dy++) {
#pragma unroll
        for (int dx = 0; dx < 2; dx++) {
            int Y = 2 * y + dy, X = 2 * x + dx;
            float s = bz;
#pragma unroll
            for (int ky = 0; ky < 3; ky++) {
                int iy = Y + ky - 1;
                if (iy < 0 || iy >= 28) continue;
#pragma unroll
                for (int kx = 0; kx < 3; kx++) {
                    int ix = X + kx - 1;
                    if (ix < 0 || ix >= 28) continue;
                    s += ip[iy * 28 + ix] * wv[ky * 3 + kx];
                }
            }
            s = fmaxf(s, 0.0f);
            m = fmaxf(m, s);
        }
    }
    out[i] = m;
}

// ---------------------------------------------------------------------------
// conv2 (16->32, 3x3 SAME) + ReLU + 2x2 maxpool fused. One block per image.
// out: (B,32,7,7) contiguous == flattened (B,1568)
// ---------------------------------------------------------------------------
__global__ __launch_bounds__(256) void conv2_pool_kernel(
    const float* __restrict__ in,   // (B,16,14,14)
    const float* __restrict__ w,    // (32,16,3,3)
    const float* __restrict__ bias, // (32,)
    float* __restrict__ out)        // (B,32,7,7)
{
    __shared__ float sin_[16 * 14 * 14];  // 3136 floats
    __shared__ float sw_[32 * 16 * 9];    // 4608 floats
    int b = blockIdx.x;
    int tid = threadIdx.x;

    for (int i = tid; i < 16 * 14 * 14; i += 256)
        sin_[i] = in[(size_t)b * (16 * 14 * 14) + i];
    for (int i = tid; i < 32 * 16 * 9; i += 256)
        sw_[i] = w[i];
    __syncthreads();

    for (int o = tid; o < 32 * 7 * 7; o += 256) {
        int c = o / 49;
        int rem = o % 49;
        int y = rem / 7;
        int x = rem % 7;
        float bz = bias[c];
        float m = 0.0f;
#pragma unroll
        for (int dy = 0; dy < 2; dy++) {
#pragma unroll
            for (int dx = 0; dx < 2; dx++) {
                int Y = 2 * y + dy, X = 2 * x + dx;
                float s = bz;
                for (int ci = 0; ci < 16; ci++) {
#pragma unroll
                    for (int ky = 0; ky < 3; ky++) {
                        int iy = Y + ky - 1;
                        if (iy < 0 || iy >= 14) continue;
#pragma unroll
                        for (int kx = 0; kx < 3; kx++) {
                            int ix = X + kx - 1;
                            if (ix < 0 || ix >= 14) continue;
                            s += sin_[ci * 196 + iy * 14 + ix] *
                                 sw_[(c * 16 + ci) * 9 + ky * 3 + kx];
                        }
                    }
                }
                s = fmaxf(s, 0.0f);
                m = fmaxf(m, s);
            }
        }
        out[(size_t)b * 1568 + o] = m;
    }
}

// ---------------------------------------------------------------------------
// Fused SGEMM: C = act((A0 [+A1] [+A2]) @ B + bias)
//   A: M x K row-major (sum of up to 3 sources), B: K x N row-major.
//   BM x 64 tile, BK=16, 256 threads, TM x 4 per-thread micro-tile.
//   Register-staged prefetch (single smem buffer, LDGs overlap compute).
//   Requirements: M % BM == 0, K % 16 == 0, K % 4 == 0, A 16B aligned.
//   N handled with guards (supports N=10 head).
// ---------------------------------------------------------------------------
template <int BM, int TM>
__global__ __launch_bounds__(256) void gemm_kernel(
    const float* __restrict__ A0, const float* __restrict__ A1,
    const float* __restrict__ A2, const float* __restrict__ B,
    const float* __restrict__ bias, float* __restrict__ C,
    int M, int N, int K, int doRelu)
{
    constexpr int BN = 64, BK = 16;
    constexpr int LA = (BM * BK) / (256 * 4);  // float4 A loads per thread

    __shared__ __align__(16) float As[BK][BM];
    __shared__ __align__(16) float Bs[BK][BN];

    const int tid = threadIdx.x;
    const int bm = blockIdx.y * BM;
    const int bn = blockIdx.x * BN;
    const int tx = tid & 15;
    const int ty = tid >> 4;
    const int n0 = tx * 4;
    const int m0 = ty * TM;
    const int bRow = tid >> 4;
    const int bCol = (tid & 15) * 4;

    float acc[TM][4];
#pragma unroll
    for (int i = 0; i < TM; i++)
#pragma unroll
        for (int j = 0; j < 4; j++) acc[i][j] = 0.0f;

    float4 ra[LA];
    float rb[4];
    const int KT = K / BK;

    // ---- prologue: load tile 0 into registers, then smem ----
#pragma unroll
    for (int i = 0; i < LA; i++) {
        int idx4 = tid + i * 256;
        int r = idx4 >> 2, c = (idx4 & 3) << 2;
        size_t off = (size_t)(bm + r) * K + c;
        float4 v = *(const float4*)(A0 + off);
        if (A1) { float4 u = *(const float4*)(A1 + off); v.x += u.x; v.y += u.y; v.z += u.z; v.w += u.w; }
        if (A2) { float4 u = *(const float4*)(A2 + off); v.x += u.x; v.y += u.y; v.z += u.z; v.w += u.w; }
        ra[i] = v;
    }
#pragma unroll
    for (int j = 0; j < 4; j++) {
        int col = bn + bCol + j;
        rb[j] = (col < N) ? B[(size_t)bRow * N + col] : 0.0f;
    }
#pragma unroll
    for (int i = 0; i < LA; i++) {
        int idx4 = tid + i * 256;
        int r = idx4 >> 2, c = (idx4 & 3) << 2;
        As[c + 0][r] = ra[i].x; As[c + 1][r] = ra[i].y;
        As[c + 2][r] = ra[i].z; As[c + 3][r] = ra[i].w;
    }
#pragma unroll
    for (int j = 0; j < 4; j++) Bs[bRow][bCol + j] = rb[j];
    __syncthreads();

    for (int kt = 0; kt < KT; kt++) {
        const int k0n = (kt + 1) * BK;
        const bool havenext = (kt + 1 < KT);
        if (havenext) {
#pragma unroll
            for (int i = 0; i < LA; i++) {
                int idx4 = tid + i * 256;
                int r = idx4 >> 2, c = (idx4 & 3) << 2;
                size_t off = (size_t)(bm + r) * K + k0n + c;
                float4 v = *(const float4*)(A0 + off);
                if (A1) { float4 u = *(const float4*)(A1 + off); v.x += u.x; v.y += u.y; v.z += u.z; v.w += u.w; }
                if (A2) { float4 u = *(const float4*)(A2 + off); v.x += u.x; v.y += u.y; v.z += u.z; v.w += u.w; }
                ra[i] = v;
            }
#pragma unroll
            for (int j = 0; j < 4; j++) {
                int col = bn + bCol + j;
                rb[j] = (col < N) ? B[(size_t)(k0n + bRow) * N + col] : 0.0f;
            }
        }
        // ---- compute current tile ----
#pragma unroll
        for (int k = 0; k < BK; k++) {
            float a[TM], b4[4];
#pragma unroll
            for (int i = 0; i < TM; i += 4) {
                float4 av = *(const float4*)&As[k][m0 + i];
                a[i] = av.x; a[i + 1] = av.y; a[i + 2] = av.z; a[i + 3] = av.w;
            }
            float4 bv = *(const float4*)&Bs[k][n0];
            b4[0] = bv.x; b4[1] = bv.y; b4[2] = bv.z; b4[3] = bv.w;
#pragma unroll
            for (int i = 0; i < TM; i++)
#pragma unroll
                for (int j = 0; j < 4; j++) acc[i][j] += a[i] * b4[j];
        }
        __syncthreads();
        if (havenext) {
#pragma unroll
            for (int i = 0; i < LA; i++) {
                int idx4 = tid + i * 256;
                int r = idx4 >> 2, c = (idx4 & 3) << 2;
                As[c + 0][r] = ra[i].x; As[c + 1][r] = ra[i].y;
                As[c + 2][r] = ra[i].z; As[c + 3][r] = ra[i].w;
            }
#pragma unroll
            for (int j = 0; j < 4; j++) Bs[bRow][bCol + j] = rb[j];
            __syncthreads();
        }
    }

    // ---- epilogue: bias + optional relu ----
#pragma unroll
    for (int i = 0; i < TM; i++) {
        int row = bm + m0 + i;
#pragma unroll
        for (int j = 0; j < 4; j++) {
            int col = bn + n0 + j;
            if (col < N) {
                float v = acc[i][j] + bias[col];
                if (doRelu) v = fmaxf(v, 0.0f);
                C[(size_t)row * N + col] = v;
            }
        }
    }
}

// ---------------------------------------------------------------------------
// Copy the two embeddings into working state
// ---------------------------------------------------------------------------
__global__ void copy2_kernel(const float* __restrict__ a, const float* __restrict__ b,
                             float* __restrict__ da, float* __restrict__ db, int n)
{
    int i = blockIdx.x * blockDim.x + threadIdx.x;
    if (i < n) { da[i] = a[i]; db[i] = b[i]; }
}

// ---------------------------------------------------------------------------
// kernel_launch
// ---------------------------------------------------------------------------
extern "C" void kernel_launch(void* const* d_in, const int* in_sizes, int n_in,
                              void* d_out, int out_size)
{
    (void)in_sizes; (void)n_in; (void)out_size;
    const float* raw = (const float*)d_in[0];
    const float* oe  = (const float*)d_in[1];
    const float* le  = (const float*)d_in[2];
    const float* c1w = (const float*)d_in[3];
    const float* c1b = (const float*)d_in[4];
    const float* c2w = (const float*)d_in[5];
    const float* c2b = (const float*)d_in[6];
    const float* pw1 = (const float*)d_in[7];
    const float* pb1 = (const float*)d_in[8];
    const float* pw2 = (const float*)d_in[9];
    const float* pb2 = (const float*)d_in[10];
    const float* bw1 = (const float*)d_in[11];
    const float* bb1 = (const float*)d_in[12];
    const float* bw2 = (const float*)d_in[13];
    const float* bb2 = (const float*)d_in[14];
    const float* hw  = (const float*)d_in[15];
    const float* hb  = (const float*)d_in[16];
    float* out = (float*)d_out;

    float *pool1, *pool2, *t1, *inp, *po, *pl;
    cudaGetSymbolAddress((void**)&pool1, g_pool1);
    cudaGetSymbolAddress((void**)&pool2, g_pool2);
    cudaGetSymbolAddress((void**)&t1,    g_t1);
    cudaGetSymbolAddress((void**)&inp,   g_inp);
    cudaGetSymbolAddress((void**)&po,    g_out);
    cudaGetSymbolAddress((void**)&pl,    g_lat);

    // CNN extractor
    {
        const int total = BATCH * 16 * 14 * 14;
        conv1_pool_kernel<<<(total + 255) / 256, 256>>>(raw, c1w, c1b, pool1);
    }
    conv2_pool_kernel<<<BATCH, 256>>>(pool1, c2w, c2b, pool2);

    // inp = relu(relu(h @ pw1 + pb1) @ pw2 + pb2)
    gemm_kernel<128, 8><<<dim3(1024 / 64, BATCH / 128), 256>>>(
        pool2, nullptr, nullptr, pw1, pb1, t1, BATCH, 1024, 1568, 1);
    gemm_kernel<64, 4><<<dim3(512 / 64, BATCH / 64), 256>>>(
        t1, nullptr, nullptr, pw2, pb2, inp, BATCH, 512, 1024, 1);

    // out, lat <- embeddings
    copy2_kernel<<<(BATCH * 512 + 255) / 256, 256>>>(oe, le, po, pl, BATCH * 512);

    // Recursion: Nsup * T latent_recursion calls; forward values of
    // stop_gradient are identity, and logits only survives from the last call.
    const dim3 g1(1024 / 64, BATCH / 128);  // 128 CTAs: 1024-wide GEMM
    const dim3 g2(512 / 64, BATCH / 64);    // 128 CTAs: 512-wide GEMM
    for (int s = 0; s < NSUP * TSTEPS; s++) {
        for (int j = 0; j < NLAT; j++) {
            // lat = backbone(inp + out + lat)
            gemm_kernel<128, 8><<<g1, 256>>>(inp, po, pl, bw1, bb1, t1, BATCH, 1024, 512, 1);
            gemm_kernel<64, 4><<<g2, 256>>>(t1, nullptr, nullptr, bw2, bb2, pl, BATCH, 512, 1024, 1);
        }
        // out = backbone(lat + inp)
        gemm_kernel<128, 8><<<g1, 256>>>(pl, inp, nullptr, bw1, bb1, t1, BATCH, 1024, 512, 1);
        gemm_kernel<64, 4><<<g2, 256>>>(t1, nullptr, nullptr, bw2, bb2, po, BATCH, 512, 1024, 1);
    }

    // logits = out @ head_w + head_b   (N = 10, guarded)
    gemm_kernel<64, 4><<<dim3(1, BATCH / 64), 256>>>(
        po, nullptr, nullptr, hw, hb, out, BATCH, 10, 512, 0);
}

// round 2
// speedup vs baseline: 1.0046x; 1.0046x over previous
#include <cuda_runtime.h>
#include <cuda_bf16.h>
#include <math.h>

// ---------------------------------------------------------------------------
// Problem constants (fixed by setup_inputs)
// ---------------------------------------------------------------------------
#define BATCH 1024
#define NSUP 16
#define TSTEPS 3
#define NLAT 6

// ---------------------------------------------------------------------------
// Scratch buffers (__device__ globals; no allocation allowed)
// ---------------------------------------------------------------------------
__device__ __align__(256) float g_pool1[BATCH * 16 * 14 * 14];   // 12.8 MB
__device__ __align__(256) float g_pool2[BATCH * 32 * 7 * 7];     // 6.4 MB (== flattened h)
__device__ __align__(256) float g_t1[BATCH * 1024];              // mid activations
__device__ __align__(256) float g_inp[BATCH * 512];
__device__ __align__(256) float g_out[BATCH * 512];
__device__ __align__(256) float g_lat[BATCH * 512];

// ---------------------------------------------------------------------------
// conv1 (1->16, 3x3 SAME) + ReLU + 2x2 maxpool fused.  out: (B,16,14,14)
// ---------------------------------------------------------------------------
__global__ void conv1_pool_kernel(const float* __restrict__ in,
                                  const float* __restrict__ w,
                                  const float* __restrict__ bias,
                                  float* __restrict__ out)
{
    int i = blockIdx.x * blockDim.x + threadIdx.x;
    const int total = BATCH * 16 * 14 * 14;
    if (i >= total) return;
    int x = i % 14;
    int y = (i / 14) % 14;
    int c = (i / 196) % 16;
    int b = i / (196 * 16);

    float wv[9];
#pragma unroll
    for (int j = 0; j < 9; j++) wv[j] = w[c * 9 + j];
    float bz = bias[c];
    const float* ip = in + (size_t)b * 784;

    float m = 0.0f;  // relu clamps each candidate to >= 0
#pragma unroll
    for (int dy = 0; dy < 2; dy++) {
#pragma unroll
        for (int dx = 0; dx < 2; dx++) {
            int Y = 2 * y + dy, X = 2 * x + dx;
            float s = bz;
#pragma unroll
            for (int ky = 0; ky < 3; ky++) {
                int iy = Y + ky - 1;
                if (iy < 0 || iy >= 28) continue;
#pragma unroll
                for (int kx = 0; kx < 3; kx++) {
                    int ix = X + kx - 1;
                    if (ix < 0 || ix >= 28) continue;
                    s += ip[iy * 28 + ix] * wv[ky * 3 + kx];
                }
            }
            s = fmaxf(s, 0.0f);
            m = fmaxf(m, s);
        }
    }
    out[i] = m;
}

// ---------------------------------------------------------------------------
// conv2 (16->32, 3x3 SAME) + ReLU + 2x2 maxpool fused. One block per image.
// out: (B,32,7,7) contiguous == flattened (B,1568)
// ---------------------------------------------------------------------------
__global__ __launch_bounds__(256) void conv2_pool_kernel(
    const float* __restrict__ in,   // (B,16,14,14)
    const float* __restrict__ w,    // (32,16,3,3)
    const float* __restrict__ bias, // (32,)
    float* __restrict__ out)        // (B,32,7,7)
{
    __shared__ float sin_[16 * 14 * 14];  // 3136 floats
    __shared__ float sw_[32 * 16 * 9];    // 4608 floats
    int b = blockIdx.x;
    int tid = threadIdx.x;

    for (int i = tid; i < 16 * 14 * 14; i += 256)
        sin_[i] = in[(size_t)b * (16 * 14 * 14) + i];
    for (int i = tid; i < 32 * 16 * 9; i += 256)
        sw_[i] = w[i];
    __syncthreads();

    for (int o = tid; o < 32 * 7 * 7; o += 256) {
        int c = o / 49;
        int rem = o % 49;
        int y = rem / 7;
        int x = rem % 7;
        float bz = bias[c];
        float m = 0.0f;
#pragma unroll
        for (int dy = 0; dy < 2; dy++) {
#pragma unroll
            for (int dx = 0; dx < 2; dx++) {
                int Y = 2 * y + dy, X = 2 * x + dx;
                float s = bz;
                for (int ci = 0; ci < 16; ci++) {
#pragma unroll
                    for (int ky = 0; ky < 3; ky++) {
                        int iy = Y + ky - 1;
                        if (iy < 0 || iy >= 14) continue;
#pragma unroll
                        for (int kx = 0; kx < 3; kx++) {
                            int ix = X + kx - 1;
                            if (ix < 0 || ix >= 14) continue;
                            s += sin_[ci * 196 + iy * 14 + ix] *
                                 sw_[(c * 16 + ci) * 9 + ky * 3 + kx];
                        }
                    }
                }
                s = fmaxf(s, 0.0f);
                m = fmaxf(m, s);
            }
        }
        out[(size_t)b * 1568 + o] = m;
    }
}

// ---------------------------------------------------------------------------
// Fused SGEMM: C = act((A0 [+A1] [+A2]) @ B + bias)
//   A: M x K row-major (sum of up to 3 sources), B: K x N row-major.
//   BM x 64 tile, BK=16, 256 threads, TM x 4 per-thread micro-tile.
//   Register-staged prefetch (single smem buffer, LDGs overlap compute).
//   Requirements: M % BM == 0, K % 16 == 0, K % 4 == 0, A 16B aligned.
//   N handled with guards (supports N=10 head).
// ---------------------------------------------------------------------------
template <int BM, int TM>
__global__ __launch_bounds__(256) void gemm_kernel(
    const float* __restrict__ A0, const float* __restrict__ A1,
    const float* __restrict__ A2, const float* __restrict__ B,
    const float* __restrict__ bias, float* __restrict__ C,
    int M, int N, int K, int doRelu)
{
    constexpr int BN = 64, BK = 16;
    constexpr int LA = (BM * BK) / (256 * 4);  // float4 A loads per thread

    __shared__ __align__(16) float As[BK][BM];
    __shared__ __align__(16) float Bs[BK][BN];

    const int tid = threadIdx.x;
    const int bm = blockIdx.y * BM;
    const int bn = blockIdx.x * BN;
    const int tx = tid & 15;
    const int ty = tid >> 4;
    const int n0 = tx * 4;
    const int m0 = ty * TM;
    const int bRow = tid >> 4;
    const int bCol = (tid & 15) * 4;

    float acc[TM][4];
#pragma unroll
    for (int i = 0; i < TM; i++)
#pragma unroll
        for (int j = 0; j < 4; j++) acc[i][j] = 0.0f;

    float4 ra[LA];
    float rb[4];
    const int KT = K / BK;

    // ---- prologue: load tile 0 into registers, then smem ----
#pragma unroll
    for (int i = 0; i < LA; i++) {
        int idx4 = tid + i * 256;
        int r = idx4 >> 2, c = (idx4 & 3) << 2;
        size_t off = (size_t)(bm + r) * K + c;
        float4 v = *(const float4*)(A0 + off);
        if (A1) { float4 u = *(const float4*)(A1 + off); v.x += u.x; v.y += u.y; v.z += u.z; v.w += u.w; }
        if (A2) { float4 u = *(const float4*)(A2 + off); v.x += u.x; v.y += u.y; v.z += u.z; v.w += u.w; }
        ra[i] = v;
    }
#pragma unroll
    for (int j = 0; j < 4; j++) {
        int col = bn + bCol + j;
        rb[j] = (col < N) ? B[(size_t)bRow * N + col] : 0.0f;
    }
#pragma unroll
    for (int i = 0; i < LA; i++) {
        int idx4 = tid + i * 256;
        int r = idx4 >> 2, c = (idx4 & 3) << 2;
        As[c + 0][r] = ra[i].x; As[c + 1][r] = ra[i].y;
        As[c + 2][r] = ra[i].z; As[c + 3][r] = ra[i].w;
    }
#pragma unroll
    for (int j = 0; j < 4; j++) Bs[bRow][bCol + j] = rb[j];
    __syncthreads();

    for (int kt = 0; kt < KT; kt++) {
        const int k0n = (kt + 1) * BK;
        const bool havenext = (kt + 1 < KT);
        if (havenext) {
#pragma unroll
            for (int i = 0; i < LA; i++) {
                int idx4 = tid + i * 256;
                int r = idx4 >> 2, c = (idx4 & 3) << 2;
                size_t off = (size_t)(bm + r) * K + k0n + c;
                float4 v = *(const float4*)(A0 + off);
                if (A1) { float4 u = *(const float4*)(A1 + off); v.x += u.x; v.y += u.y; v.z += u.z; v.w += u.w; }
                if (A2) { float4 u = *(const float4*)(A2 + off); v.x += u.x; v.y += u.y; v.z += u.z; v.w += u.w; }
                ra[i] = v;
            }
#pragma unroll
            for (int j = 0; j < 4; j++) {
                int col = bn + bCol + j;
                rb[j] = (col < N) ? B[(size_t)(k0n + bRow) * N + col] : 0.0f;
            }
        }
        // ---- compute current tile ----
#pragma unroll
        for (int k = 0; k < BK; k++) {
            float a[TM], b4[4];
#pragma unroll
            for (int i = 0; i < TM; i += 4) {
                float4 av = *(const float4*)&As[k][m0 + i];
                a[i] = av.x; a[i + 1] = av.y; a[i + 2] = av.z; a[i + 3] = av.w;
            }
            float4 bv = *(const float4*)&Bs[k][n0];
            b4[0] = bv.x; b4[1] = bv.y; b4[2] = bv.z; b4[3] = bv.w;
#pragma unroll
            for (int i = 0; i < TM; i++)
#pragma unroll
                for (int j = 0; j < 4; j++) acc[i][j] += a[i] * b4[j];
        }
        __syncthreads();
        if (havenext) {
#pragma unroll
            for (int i = 0; i < LA; i++) {
                int idx4 = tid + i * 256;
                int r = idx4 >> 2, c = (idx4 & 3) << 2;
                As[c + 0][r] = ra[i].x; As[c + 1][r] = ra[i].y;
                As[c + 2][r] = ra[i].z; As[c + 3][r] = ra[i].w;
            }
#pragma unroll
            for (int j = 0; j < 4; j++) Bs[bRow][bCol + j] = rb[j];
            __syncthreads();
        }
    }

    // ---- epilogue: bias + optional relu ----
#pragma unroll
    for (int i = 0; i < TM; i++) {
        int row = bm + m0 + i;
#pragma unroll
        for (int j = 0; j < 4; j++) {
            int col = bn + n0 + j;
            if (col < N) {
                float v = acc[i][j] + bias[col];
                if (doRelu) v = fmaxf(v, 0.0f);
                C[(size_t)row * N + col] = v;
            }
        }
    }
}

// ---------------------------------------------------------------------------
// Copy the two embeddings into working state
// ---------------------------------------------------------------------------
__global__ void copy2_kernel(const float* __restrict__ a, const float* __restrict__ b,
                             float* __restrict__ da, float* __restrict__ db, int n)
{
    int i = blockIdx.x * blockDim.x + threadIdx.x;
    if (i < n) { da[i] = a[i]; db[i] = b[i]; }
}

// ---------------------------------------------------------------------------
// kernel_launch
// ---------------------------------------------------------------------------
extern "C" void kernel_launch(void* const* d_in, const int* in_sizes, int n_in,
                              void* d_out, int out_size)
{
    (void)in_sizes; (void)n_in; (void)out_size;
    const float* raw = (const float*)d_in[0];
    const float* oe  = (const float*)d_in[1];
    const float* le  = (const float*)d_in[2];
    const float* c1w = (const float*)d_in[3];
    const float* c1b = (const float*)d_in[4];
    const float* c2w = (const float*)d_in[5];
    const float* c2b = (const float*)d_in[6];
    const float* pw1 = (const float*)d_in[7];
    const float* pb1 = (const float*)d_in[8];
    const float* pw2 = (const float*)d_in[9];
    const float* pb2 = (const float*)d_in[10];
    const float* bw1 = (const float*)d_in[11];
    const float* bb1 = (const float*)d_in[12];
    const float* bw2 = (const float*)d_in[13];
    const float* bb2 = (const float*)d_in[14];
    const float* hw  = (const float*)d_in[15];
    const float* hb  = (const float*)d_in[16];
    float* out = (float*)d_out;

    float *pool1, *pool2, *t1, *inp, *po, *pl;
    cudaGetSymbolAddress((void**)&pool1, g_pool1);
    cudaGetSymbolAddress((void**)&pool2, g_pool2);
    cudaGetSymbolAddress((void**)&t1,    g_t1);
    cudaGetSymbolAddress((void**)&inp,   g_inp);
    cudaGetSymbolAddress((void**)&po,    g_out);
    cudaGetSymbolAddress((void**)&pl,    g_lat);

    // CNN extractor
    {
        const int total = BATCH * 16 * 14 * 14;
        conv1_pool_kernel<<<(total + 255) / 256, 256>>>(raw, c1w, c1b, pool1);
    }
    conv2_pool_kernel<<<BATCH, 256>>>(pool1, c2w, c2b, pool2);

    // inp = relu(relu(h @ pw1 + pb1) @ pw2 + pb2)
    gemm_kernel<128, 8><<<dim3(1024 / 64, BATCH / 128), 256>>>(
        pool2, nullptr, nullptr, pw1, pb1, t1, BATCH, 1024, 1568, 1);
    gemm_kernel<64, 4><<<dim3(512 / 64, BATCH / 64), 256>>>(
        t1, nullptr, nullptr, pw2, pb2, inp, BATCH, 512, 1024, 1);

    // out, lat <- embeddings
    copy2_kernel<<<(BATCH * 512 + 255) / 256, 256>>>(oe, le, po, pl, BATCH * 512);

    // Recursion: Nsup * T latent_recursion calls; forward values of
    // stop_gradient are identity, and logits only survives from the last call.
    const dim3 g1(1024 / 64, BATCH / 128);  // 128 CTAs: 1024-wide GEMM
    const dim3 g2(512 / 64, BATCH / 64);    // 128 CTAs: 512-wide GEMM
    for (int s = 0; s < NSUP * TSTEPS; s++) {
        for (int j = 0; j < NLAT; j++) {
            // lat = backbone(inp + out + lat)
            gemm_kernel<128, 8><<<g1, 256>>>(inp, po, pl, bw1, bb1, t1, BATCH, 1024, 512, 1);
            gemm_kernel<64, 4><<<g2, 256>>>(t1, nullptr, nullptr, bw2, bb2, pl, BATCH, 512, 1024, 1);
        }
        // out = backbone(lat + inp)
        gemm_kernel<128, 8><<<g1, 256>>>(pl, inp, nullptr, bw1, bb1, t1, BATCH, 1024, 512, 1);
        gemm_kernel<64, 4><<<g2, 256>>>(t1, nullptr, nullptr, bw2, bb2, po, BATCH, 512, 1024, 1);
    }

    // logits = out @ head_w + head_b   (N = 10, guarded)
    gemm_kernel<64, 4><<<dim3(1, BATCH / 64), 256>>>(
        po, nullptr, nullptr, hw, hb, out, BATCH, 10, 512, 0);
}

// round 10
// speedup vs baseline: 1.6594x; 1.6517x over previous
#include <cuda_runtime.h>
#include <cuda_bf16.h>
#include <mma.h>
#include <cstdint>
#include <math.h>

using namespace nvcuda;
typedef __nv_bfloat16 bf16;

#define BATCH 1024
#define NSUP 16
#define NLAT 6

// ---- scratch (__device__ globals; allocation forbidden) ----
__device__ __align__(256) float g_pool1[BATCH * 16 * 14 * 14];
__device__ __align__(256) float g_pool2[BATCH * 32 * 7 * 7];
__device__ __align__(256) float g_t1f [BATCH * 1024];
__device__ __align__(256) float g_inp [BATCH * 512];
__device__ __align__(256) float g_io  [BATCH * 512];   // inp + out
__device__ __align__(256) float g_li  [BATCH * 512];   // inp + lat
__device__ __align__(256) float g_outf[BATCH * 512];
__device__ __align__(256) bf16 g_w1h[1024 * 512];      // W1^T hi (N x K)
__device__ __align__(256) bf16 g_w1l[1024 * 512];      // W1^T lo
__device__ __align__(256) bf16 g_w2h[512 * 1024];      // W2^T hi
__device__ __align__(256) bf16 g_w2l[512 * 1024];      // W2^T lo
__device__ __align__(256) bf16 g_sah[BATCH * 512];
__device__ __align__(256) bf16 g_sal[BATCH * 512];
__device__ __align__(256) bf16 g_t1h[BATCH * 1024];
__device__ __align__(256) bf16 g_t1l[BATCH * 1024];

// ===========================================================================
// bf16-split WMMA GEMM.  C = relu((Ah+Al) @ (Bh+Bl)^T + bias), fp32 acc,
// 3 wmma per tile: Ah*Bh + Al*Bh + Ah*Bl  (Al*Bl ~2^-18 rel, dropped).
// bf16 carries fp32's exponent range -> immune to the activation explosion
// that overflowed f16 (max 65504) in the deep recursion.
// Epilogue (scalar, layout-free): stage C to smem via store_matrix_sync, then
//   (Chi,Clo) = split_bf16(relu_out + add_pair?)  [always]
//   aux_out   = relu_out + add_aux                [optional]
//   act_out   = relu_out                          [optional]
// A: M x K bf16 pair row-major; B: N x K bf16 pair (pre-transposed weights;
// N x K row-major == wmma col_major KxN with ldm=RS).
// Tile 64x64x64, 8 warps (2 in M x 4 in N). Static smem 41.2KB.
// ===========================================================================
__global__ __launch_bounds__(256, 1) void wmma_gemm(
    const bf16* __restrict__ Ahi, const bf16* __restrict__ Alo,
    const bf16* __restrict__ Bhi, const bf16* __restrict__ Blo,
    const float* __restrict__ bias,
    const float* __restrict__ add_pair, const float* __restrict__ add_aux,
    bf16* __restrict__ Chi, bf16* __restrict__ Clo,
    float* __restrict__ aux_out, float* __restrict__ act_out,
    int N, int K)
{
    constexpr int RS = 80;                 // row stride in bf16 (160B rows, 32B-aligned)
    __shared__ float sbias[64];
    __shared__ __align__(32) bf16 stile[4 * 64 * RS];   // 40960 B
    bf16* sAh = stile;
    bf16* sAl = stile + 64 * RS;
    bf16* sBh = stile + 2 * 64 * RS;
    bf16* sBl = stile + 3 * 64 * RS;

    const int tid = threadIdx.x, wid = tid >> 5;
    const int bm = blockIdx.y * 64, bn = blockIdx.x * 64;
    const int warp_m = wid & 1, warp_n = wid >> 1;   // 2 x 4 warp grid
    const int m_w = warp_m * 32, n_w = warp_n * 16;
    const int KT = K >> 6;

    if (tid < 64) sbias[tid] = bias[bn + tid];

    wmma::fragment<wmma::accumulator, 16, 16, 16, float> facc[2];
    wmma::fill_fragment(facc[0], 0.0f);
    wmma::fill_fragment(facc[1], 0.0f);

    uint4 rah[2], ral[2], rbh[2], rbl[2];

    auto gload = [&](int kt) {
        const int kof = kt * 64;
#pragma unroll
        for (int i = 0; i < 2; i++) {
            int idx = tid + i * 256; int row = idx >> 3, ch = idx & 7;
            size_t oa = (size_t)(bm + row) * K + kof + ch * 8;
            size_t ob = (size_t)(bn + row) * K + kof + ch * 8;
            rah[i] = *(const uint4*)(Ahi + oa);
            ral[i] = *(const uint4*)(Alo + oa);
            rbh[i] = *(const uint4*)(Bhi + ob);
            rbl[i] = *(const uint4*)(Blo + ob);
        }
    };
    auto sstore = [&]() {
#pragma unroll
        for (int i = 0; i < 2; i++) {
            int idx = tid + i * 256; int row = idx >> 3, ch = idx & 7;
            *(uint4*)(sAh + row * RS + ch * 8) = rah[i];
            *(uint4*)(sAl + row * RS + ch * 8) = ral[i];
            *(uint4*)(sBh + row * RS + ch * 8) = rbh[i];
            *(uint4*)(sBl + row * RS + ch * 8) = rbl[i];
        }
    };

    gload(0);
    sstore();
    __syncthreads();

    for (int kt = 0; kt < KT; kt++) {
        if (kt + 1 < KT) gload(kt + 1);   // prefetch next tile into registers

#pragma unroll
        for (int k16 = 0; k16 < 4; k16++) {
            const int kb = k16 * 16;
            wmma::fragment<wmma::matrix_a, 16, 16, 16, bf16, wmma::row_major> fah, fal;
            wmma::fragment<wmma::matrix_b, 16, 16, 16, bf16, wmma::col_major> fbh, fbl;
            wmma::load_matrix_sync(fbh, sBh + n_w * RS + kb, RS);
            wmma::load_matrix_sync(fbl, sBl + n_w * RS + kb, RS);
#pragma unroll
            for (int ti = 0; ti < 2; ti++) {
                wmma::load_matrix_sync(fah, sAh + (m_w + ti * 16) * RS + kb, RS);
                wmma::load_matrix_sync(fal, sAl + (m_w + ti * 16) * RS + kb, RS);
                wmma::mma_sync(facc[ti], fah, fbh, facc[ti]);
                wmma::mma_sync(facc[ti], fal, fbh, facc[ti]);
                wmma::mma_sync(facc[ti], fah, fbl, facc[ti]);
            }
        }
        __syncthreads();
        if (kt + 1 < KT) { sstore(); __syncthreads(); }
    }

    // ---- stage C to smem (aliases tile memory; safe after the sync above) ----
    float* cs = (float*)stile;   // 64x64 f32 = 16384B <= 40960B
    wmma::store_matrix_sync(cs + (m_w +  0) * 64 + n_w, facc[0], 64, wmma::mem_row_major);
    wmma::store_matrix_sync(cs + (m_w + 16) * 64 + n_w, facc[1], 64, wmma::mem_row_major);
    __syncthreads();

    // ---- scalar, layout-free fused epilogue ----
    for (int idx = tid; idx < 64 * 64; idx += 256) {
        int row = idx >> 6, col = idx & 63;
        float v = fmaxf(cs[idx] + sbias[col], 0.0f);
        size_t ob = (size_t)(bm + row) * N + bn + col;
        float p = v;
        if (add_pair) p += add_pair[ob];
        bf16 h = __float2bfloat16_rn(p);
        Chi[ob] = h;
        Clo[ob] = __float2bfloat16_rn(p - __bfloat162float(h));
        if (aux_out) aux_out[ob] = add_aux[ob] + v;
        if (act_out) act_out[ob] = v;
    }
}

// ---- W (KxN f32) -> W^T (NxK) bf16 hi/lo pair ----
__global__ void transpose_split(const float* __restrict__ W,
                                bf16* __restrict__ Th, bf16* __restrict__ Tl,
                                int K, int N)
{
    __shared__ float t[32][33];
    int nb = blockIdx.x * 32, kb = blockIdx.y * 32;
    int tx = threadIdx.x, ty = threadIdx.y;
#pragma unroll
    for (int i = 0; i < 32; i += 8)
        t[ty + i][tx] = W[(size_t)(kb + ty + i) * N + nb + tx];
    __syncthreads();
#pragma unroll
    for (int i = 0; i < 32; i += 8) {
        int n = nb + ty + i, k = kb + tx;
        float v = t[tx][ty + i];
        bf16 h = __float2bfloat16_rn(v);
        Th[(size_t)n * K + k] = h;
        Tl[(size_t)n * K + k] = __float2bfloat16_rn(v - __bfloat162float(h));
    }
}

// io = inp + oe ; sA = split(io + le)
__global__ void setup_state(const float* __restrict__ inp, const float* __restrict__ oe,
                            const float* __restrict__ le, float* __restrict__ io,
                            bf16* __restrict__ shi, bf16* __restrict__ slo)
{
    int i = blockIdx.x * 256 + threadIdx.x;
    if (i >= BATCH * 512) return;
    float v = inp[i] + oe[i];
    io[i] = v;
    float s = v + le[i];
    bf16 h = __float2bfloat16_rn(s);
    shi[i] = h;
    slo[i] = __float2bfloat16_rn(s - __bfloat162float(h));
}

// ---- conv1 + relu + pool ----
__global__ void conv1_pool_kernel(const float* __restrict__ in, const float* __restrict__ w,
                                  const float* __restrict__ bias, float* __restrict__ out)
{
    int i = blockIdx.x * blockDim.x + threadIdx.x;
    if (i >= BATCH * 16 * 196) return;
    int x = i % 14, y = (i / 14) % 14, c = (i / 196) % 16, b = i / 3136;
    float wv[9];
#pragma unroll
    for (int j = 0; j < 9; j++) wv[j] = w[c * 9 + j];
    float bz = bias[c], m = 0.0f;
    const float* ip = in + (size_t)b * 784;
#pragma unroll
    for (int dy = 0; dy < 2; dy++)
#pragma unroll
        for (int dx = 0; dx < 2; dx++) {
            int Y = 2 * y + dy, X = 2 * x + dx;
            float s = bz;
#pragma unroll
            for (int ky = 0; ky < 3; ky++) {
                int iy = Y + ky - 1; if (iy < 0 || iy >= 28) continue;
#pragma unroll
                for (int kx = 0; kx < 3; kx++) {
                    int ix = X + kx - 1; if (ix < 0 || ix >= 28) continue;
                    s += ip[iy * 28 + ix] * wv[ky * 3 + kx];
                }
            }
            m = fmaxf(m, fmaxf(s, 0.0f));
        }
    out[i] = m;
}

__global__ __launch_bounds__(256) void conv2_pool_kernel(
    const float* __restrict__ in, const float* __restrict__ w,
    const float* __restrict__ bias, float* __restrict__ out)
{
    __shared__ float sin_[3136];
    __shared__ float sw_[4608];
    int b = blockIdx.x, tid = threadIdx.x;
    for (int i = tid; i < 3136; i += 256) sin_[i] = in[(size_t)b * 3136 + i];
    for (int i = tid; i < 4608; i += 256) sw_[i] = w[i];
    __syncthreads();
    for (int o = tid; o < 32 * 49; o += 256) {
        int c = o / 49, rem = o % 49, y = rem / 7, x = rem % 7;
        float bz = bias[c], m = 0.0f;
#pragma unroll
        for (int dy = 0; dy < 2; dy++)
#pragma unroll
            for (int dx = 0; dx < 2; dx++) {
                int Y = 2 * y + dy, X = 2 * x + dx;
                float s = bz;
                for (int ci = 0; ci < 16; ci++)
#pragma unroll
                    for (int ky = 0; ky < 3; ky++) {
                        int iy = Y + ky - 1; if (iy < 0 || iy >= 14) continue;
#pragma unroll
                        for (int kx = 0; kx < 3; kx++) {
                            int ix = X + kx - 1; if (ix < 0 || ix >= 14) continue;
                            s += sin_[ci * 196 + iy * 14 + ix] * sw_[(c * 16 + ci) * 9 + ky * 3 + kx];
                        }
                    }
                m = fmaxf(m, fmaxf(s, 0.0f));
            }
        out[(size_t)b * 1568 + o] = m;
    }
}

// ---- fp32 SGEMM (proj + head only) ----
template <int BM, int TM>
__global__ __launch_bounds__(256) void gemm_kernel(
    const float* __restrict__ A0, const float* __restrict__ B,
    const float* __restrict__ bias, float* __restrict__ C,
    int M, int N, int K, int doRelu)
{
    constexpr int BN = 64, BK = 16;
    constexpr int LA = (BM * BK) / 1024;
    __shared__ __align__(16) float As[BK][BM];
    __shared__ __align__(16) float Bs[BK][BN];
    const int tid = threadIdx.x;
    const int bm = blockIdx.y * BM, bn = blockIdx.x * BN;
    const int n0 = (tid & 15) * 4, m0 = (tid >> 4) * TM;
    const int bRow = tid >> 4, bCol = (tid & 15) * 4;
    float acc[TM][4] = {};
    float4 ra[LA]; float rb[4];
    const int KT = K / BK;
#pragma unroll
    for (int i = 0; i < LA; i++) {
        int idx4 = tid + i * 256; int r = idx4 >> 2, c = (idx4 & 3) << 2;
        ra[i] = *(const float4*)(A0 + (size_t)(bm + r) * K + c);
    }
#pragma unroll
    for (int j = 0; j < 4; j++) {
        int col = bn + bCol + j;
        rb[j] = (col < N) ? B[(size_t)bRow * N + col] : 0.0f;
    }
#pragma unroll
    for (int i = 0; i < LA; i++) {
        int idx4 = tid + i * 256; int r = idx4 >> 2, c = (idx4 & 3) << 2;
        As[c][r] = ra[i].x; As[c+1][r] = ra[i].y; As[c+2][r] = ra[i].z; As[c+3][r] = ra[i].w;
    }
#pragma unroll
    for (int j = 0; j < 4; j++) Bs[bRow][bCol + j] = rb[j];
    __syncthreads();
    for (int kt = 0; kt < KT; kt++) {
        const int k0n = (kt + 1) * BK;
        const bool nx = (kt + 1 < KT);
        if (nx) {
#pragma unroll
            for (int i = 0; i < LA; i++) {
                int idx4 = tid + i * 256; int r = idx4 >> 2, c = (idx4 & 3) << 2;
                ra[i] = *(const float4*)(A0 + (size_t)(bm + r) * K + k0n + c);
            }
#pragma unroll
            for (int j = 0; j < 4; j++) {
                int col = bn + bCol + j;
                rb[j] = (col < N) ? B[(size_t)(k0n + bRow) * N + col] : 0.0f;
            }
        }
#pragma unroll
        for (int k = 0; k < BK; k++) {
            float a[TM], b4[4];
#pragma unroll
            for (int i = 0; i < TM; i += 4) {
                float4 av = *(const float4*)&As[k][m0 + i];
                a[i] = av.x; a[i+1] = av.y; a[i+2] = av.z; a[i+3] = av.w;
            }
            float4 bv = *(const float4*)&Bs[k][n0];
            b4[0] = bv.x; b4[1] = bv.y; b4[2] = bv.z; b4[3] = bv.w;
#pragma unroll
            for (int i = 0; i < TM; i++)
#pragma unroll
                for (int j = 0; j < 4; j++) acc[i][j] += a[i] * b4[j];
        }
        __syncthreads();
        if (nx) {
#pragma unroll
            for (int i = 0; i < LA; i++) {
                int idx4 = tid + i * 256; int r = idx4 >> 2, c = (idx4 & 3) << 2;
                As[c][r] = ra[i].x; As[c+1][r] = ra[i].y; As[c+2][r] = ra[i].z; As[c+3][r] = ra[i].w;
            }
#pragma unroll
            for (int j = 0; j < 4; j++) Bs[bRow][bCol + j] = rb[j];
            __syncthreads();
        }
    }
#pragma unroll
    for (int i = 0; i < TM; i++)
#pragma unroll
        for (int j = 0; j < 4; j++) {
            int col = bn + n0 + j;
            if (col < N) {
                float v = acc[i][j] + bias[col];
                if (doRelu) v = fmaxf(v, 0.0f);
                C[(size_t)(bm + m0 + i) * N + col] = v;
            }
        }
}

extern "C" void kernel_launch(void* const* d_in, const int* in_sizes, int n_in,
                              void* d_out, int out_size)
{
    (void)in_sizes; (void)n_in; (void)out_size;
    const float* raw = (const float*)d_in[0];
    const float* oe  = (const float*)d_in[1];
    const float* le  = (const float*)d_in[2];
    const float* c1w = (const float*)d_in[3];
    const float* c1b = (const float*)d_in[4];
    const float* c2w = (const float*)d_in[5];
    const float* c2b = (const float*)d_in[6];
    const float* pw1 = (const float*)d_in[7];
    const float* pb1 = (const float*)d_in[8];
    const float* pw2 = (const float*)d_in[9];
    const float* pb2 = (const float*)d_in[10];
    const float* bw1 = (const float*)d_in[11];
    const float* bb1 = (const float*)d_in[12];
    const float* bw2 = (const float*)d_in[13];
    const float* bb2 = (const float*)d_in[14];
    const float* hw  = (const float*)d_in[15];
    const float* hb  = (const float*)d_in[16];
    float* out = (float*)d_out;

    float *pool1, *pool2, *t1f, *inp, *io, *li, *outf;
    bf16 *w1h, *w1l, *w2h, *w2l, *sah, *sal, *t1h, *t1l;
    cudaGetSymbolAddress((void**)&pool1, g_pool1);
    cudaGetSymbolAddress((void**)&pool2, g_pool2);
    cudaGetSymbolAddress((void**)&t1f, g_t1f);
    cudaGetSymbolAddress((void**)&inp, g_inp);
    cudaGetSymbolAddress((void**)&io,  g_io);
    cudaGetSymbolAddress((void**)&li,  g_li);
    cudaGetSymbolAddress((void**)&outf, g_outf);
    cudaGetSymbolAddress((void**)&w1h, g_w1h);
    cudaGetSymbolAddress((void**)&w1l, g_w1l);
    cudaGetSymbolAddress((void**)&w2h, g_w2h);
    cudaGetSymbolAddress((void**)&w2l, g_w2l);
    cudaGetSymbolAddress((void**)&sah, g_sah);
    cudaGetSymbolAddress((void**)&sal, g_sal);
    cudaGetSymbolAddress((void**)&t1h, g_t1h);
    cudaGetSymbolAddress((void**)&t1l, g_t1l);

    conv1_pool_kernel<<<(BATCH * 16 * 196 + 255) / 256, 256>>>(raw, c1w, c1b, pool1);
    conv2_pool_kernel<<<BATCH, 256>>>(pool1, c2w, c2b, pool2);
    gemm_kernel<128, 8><<<dim3(16, 8), 256>>>(pool2, pw1, pb1, t1f, BATCH, 1024, 1568, 1);
    gemm_kernel<64, 4><<<dim3(8, 16), 256>>>(t1f, pw2, pb2, inp, BATCH, 512, 1024, 1);

    transpose_split<<<dim3(32, 16), dim3(32, 8)>>>(bw1, w1h, w1l, 512, 1024);
    transpose_split<<<dim3(16, 32), dim3(32, 8)>>>(bw2, w2h, w2l, 1024, 512);
    setup_state<<<(BATCH * 512 + 255) / 256, 256>>>(inp, oe, le, io, sah, sal);

    const dim3 g1(16, 16);  // GEMM1: N=1024, M=1024, 64x64 tiles -> 256 CTAs
    const dim3 g2(8, 16);   // GEMM2: N=512,  M=1024 -> 128 CTAs
    const int STEPS = NSUP * 3;
    for (int s = 0; s < STEPS; s++) {
        for (int j = 0; j < NLAT; j++) {
            // t1 = relu(x @ W1 + b1)
            wmma_gemm<<<g1, 256>>>(sah, sal, w1h, w1l, bb1,
                nullptr, nullptr, t1h, t1l, nullptr, nullptr, 1024, 512);
            if (j < NLAT - 1)
                // lat = relu(t1@W2+b2); next x = io + lat
                wmma_gemm<<<g2, 256>>>(t1h, t1l, w2h, w2l, bb2,
                    io, nullptr, sah, sal, nullptr, nullptr, 512, 1024);
            else
                // last latent: next x = inp + lat; li = inp + lat
                wmma_gemm<<<g2, 256>>>(t1h, t1l, w2h, w2l, bb2,
                    inp, inp, sah, sal, li, nullptr, 512, 1024);
        }
        // out step: t1 = relu((inp+lat) @ W1 + b1)
        wmma_gemm<<<g1, 256>>>(sah, sal, w1h, w1l, bb1,
            nullptr, nullptr, t1h, t1l, nullptr, nullptr, 1024, 512);
        // out = relu(t1@W2+b2); next x = li + out; io = inp + out; (+outf last)
        wmma_gemm<<<g2, 256>>>(t1h, t1l, w2h, w2l, bb2,
            li, inp, sah, sal, io, (s == STEPS - 1) ? outf : nullptr, 512, 1024);
    }
    // logits = outf @ head_w + head_b
    gemm_kernel<64, 4><<<dim3(1, 16), 256>>>(outf, hw, hb, out, BATCH, 10, 512, 0);
}